// round 2
// baseline (speedup 1.0000x reference)
#include <cuda_runtime.h>

// out[row, :] = x[row, :] - sum(x[row, :])
// x: [R, 512] fp32, R = 8*8192 = 65536
// One warp per 2 rows: 8 front-batched LDG.128 per lane (MLP=8),
// two independent warp reductions, streaming (.cs) loads+stores.

static constexpr int D = 512;
static constexpr int WARPS_PER_BLOCK = 8;
static constexpr int ROWS_PER_WARP = 2;

__device__ __forceinline__ float4 ldcs4(const float4* p) {
    return __ldcs(p);
}
__device__ __forceinline__ void stcs4(float4* p, float4 v) {
    __stcs(p, v);
}

__global__ void __launch_bounds__(WARPS_PER_BLOCK * 32)
neg_sum_add_kernel(const float* __restrict__ x, float* __restrict__ out, int nrows) {
    int warp = threadIdx.x >> 5;
    int lane = threadIdx.x & 31;
    int row0 = (blockIdx.x * WARPS_PER_BLOCK + warp) * ROWS_PER_WARP;
    if (row0 >= nrows) return;

    const float4* __restrict__ xa = reinterpret_cast<const float4*>(x + (size_t)row0 * D);
    const float4* __restrict__ xb = xa + (D / 4);
    float4* __restrict__ oa = reinterpret_cast<float4*>(out + (size_t)row0 * D);
    float4* __restrict__ ob = oa + (D / 4);

    // Front-batch all 8 loads (128 float4 per row, 4 per lane per row).
    float4 a0 = ldcs4(xa + lane);
    float4 a1 = ldcs4(xa + lane + 32);
    float4 a2 = ldcs4(xa + lane + 64);
    float4 a3 = ldcs4(xa + lane + 96);
    float4 b0 = ldcs4(xb + lane);
    float4 b1 = ldcs4(xb + lane + 32);
    float4 b2 = ldcs4(xb + lane + 64);
    float4 b3 = ldcs4(xb + lane + 96);

    float sa = (a0.x + a0.y) + (a0.z + a0.w)
             + (a1.x + a1.y) + (a1.z + a1.w)
             + (a2.x + a2.y) + (a2.z + a2.w)
             + (a3.x + a3.y) + (a3.z + a3.w);
    float sb = (b0.x + b0.y) + (b0.z + b0.w)
             + (b1.x + b1.y) + (b1.z + b1.w)
             + (b2.x + b2.y) + (b2.z + b2.w)
             + (b3.x + b3.y) + (b3.z + b3.w);

    #pragma unroll
    for (int off = 16; off > 0; off >>= 1) {
        sa += __shfl_xor_sync(0xffffffffu, sa, off);
        sb += __shfl_xor_sync(0xffffffffu, sb, off);
    }

    a0.x -= sa; a0.y -= sa; a0.z -= sa; a0.w -= sa;
    a1.x -= sa; a1.y -= sa; a1.z -= sa; a1.w -= sa;
    a2.x -= sa; a2.y -= sa; a2.z -= sa; a2.w -= sa;
    a3.x -= sa; a3.y -= sa; a3.z -= sa; a3.w -= sa;
    b0.x -= sb; b0.y -= sb; b0.z -= sb; b0.w -= sb;
    b1.x -= sb; b1.y -= sb; b1.z -= sb; b1.w -= sb;
    b2.x -= sb; b2.y -= sb; b2.z -= sb; b2.w -= sb;
    b3.x -= sb; b3.y -= sb; b3.z -= sb; b3.w -= sb;

    stcs4(oa + lane,      a0);
    stcs4(oa + lane + 32, a1);
    stcs4(oa + lane + 64, a2);
    stcs4(oa + lane + 96, a3);
    stcs4(ob + lane,      b0);
    stcs4(ob + lane + 32, b1);
    stcs4(ob + lane + 64, b2);
    stcs4(ob + lane + 96, b3);
}

extern "C" void kernel_launch(void* const* d_in, const int* in_sizes, int n_in,
                              void* d_out, int out_size) {
    const float* x = (const float*)d_in[0];
    float* out = (float*)d_out;
    int nrows = in_sizes[0] / D;
    int rows_per_block = WARPS_PER_BLOCK * ROWS_PER_WARP;
    int blocks = (nrows + rows_per_block - 1) / rows_per_block;
    neg_sum_add_kernel<<<blocks, WARPS_PER_BLOCK * 32>>>(x, out, nrows);
}